// round 12
// baseline (speedup 1.0000x reference)
#include <cuda_runtime.h>
#include <cstdint>

// ---------------------------------------------------------------------------
// Problem constants (hardcoded from the reference)
// ---------------------------------------------------------------------------
#define N_B    8
#define LQ     300
#define NQ     2400        // N_B * LQ
#define C_DIM  256
#define HEADS  8
#define NLVL   4
#define NPTS   8
#define LEN_IN 21760
// level starts: 0, 16384, 20480, 21504  (sizes 128^2, 64^2, 32^2, 16^2)

// ---------------------------------------------------------------------------
// Scratch (device globals — no allocation allowed)
// ---------------------------------------------------------------------------
__device__ uint32_t g_packed[NQ * 512];          // 1-bit mask per (n,q): 128x128 bits
__device__ float    g_boxes[NQ * 4];             // cx, cy, w, h
__device__ float    g_locs[NQ * 512];            // 256 points * (x,y)
__device__ float    g_wts[NQ * 256];             // softmaxed weights
__device__ float    g_agg[NQ * 8 * 256];         // per (n,q,head): aggregated 256-vec
__device__ float    g_beta[NQ * 8];              // per (n,q,head): sum of valid corner weights
__device__ float    g_outcore[NQ * 256];         // pre-output-projection

// ---------------------------------------------------------------------------
// Kernel 1: bounding boxes + packed binary masks  (pure float4 streamer)
// grid = NQ blocks, 256 threads. Thread t handles 64 contiguous elements:
//   row = t>>1, half = t&1 (cols half*64 .. half*64+63)
// ---------------------------------------------------------------------------
__global__ __launch_bounds__(256) void kbox(const float* __restrict__ masks)
{
    int nq   = blockIdx.x;
    int tid  = threadIdx.x;
    int row  = tid >> 1;
    int half = tid & 1;

    __shared__ unsigned scol[4];   // per-x "any over y" bits (128 cols)
    __shared__ unsigned srow[4];   // per-y "any over x" bits (128 rows)
    if (tid < 4) { scol[tid] = 0u; srow[tid] = 0u; }
    __syncthreads();

    const float4* p = (const float4*)(masks + (size_t)nq * 16384 + tid * 64);

    unsigned w0 = 0u, w1 = 0u;
    #pragma unroll
    for (int j = 0; j < 8; ++j) {
        float4 v = p[j];
        unsigned b = (v.x > 0.0f ? 1u : 0u)
                   | (v.y > 0.0f ? 2u : 0u)
                   | (v.z > 0.0f ? 4u : 0u)
                   | (v.w > 0.0f ? 8u : 0u);
        w0 |= b << (j * 4);
    }
    #pragma unroll
    for (int j = 8; j < 16; ++j) {
        float4 v = p[j];
        unsigned b = (v.x > 0.0f ? 1u : 0u)
                   | (v.y > 0.0f ? 2u : 0u)
                   | (v.z > 0.0f ? 4u : 0u)
                   | (v.w > 0.0f ? 8u : 0u);
        w1 |= b << ((j - 8) * 4);
    }

    // packed mask store (coalesced: warp covers 256 contiguous bytes)
    uint32_t* pk = g_packed + (size_t)nq * 512 + row * 4 + half * 2;
    pk[0] = w0;
    pk[1] = w1;

    // column-any reduction
    if (w0) atomicOr(&scol[half * 2], w0);
    if (w1) atomicOr(&scol[half * 2 + 1], w1);

    // row-any: combine the two halves of this row (adjacent lanes)
    unsigned any = (w0 | w1) ? 1u : 0u;
    unsigned both = any | __shfl_xor_sync(0xffffffffu, any, 1);
    if (half == 0 && both)
        atomicOr(&srow[row >> 5], 1u << (row & 31));
    __syncthreads();

    if (tid == 0) {
        unsigned anyc = scol[0] | scol[1] | scol[2] | scol[3];
        float bx0 = 0.f, bx1 = 0.f, bx2 = 0.f, bx3 = 0.f;
        if (anyc) {
            int xmin = 0, xmax = 0, ymin = 0, ymax = 0;
            #pragma unroll
            for (int i = 3; i >= 0; --i) if (scol[i]) xmin = i * 32 + __ffs((int)scol[i]) - 1;
            #pragma unroll
            for (int i = 0; i < 4; ++i)  if (scol[i]) xmax = i * 32 + 31 - __clz((int)scol[i]);
            #pragma unroll
            for (int i = 3; i >= 0; --i) if (srow[i]) ymin = i * 32 + __ffs((int)srow[i]) - 1;
            #pragma unroll
            for (int i = 0; i < 4; ++i)  if (srow[i]) ymax = i * 32 + 31 - __clz((int)srow[i]);
            float x0 = xmin * (1.0f / 128.0f), x1 = (xmax + 1) * (1.0f / 128.0f);
            float y0 = ymin * (1.0f / 128.0f), y1 = (ymax + 1) * (1.0f / 128.0f);
            bx0 = (x0 + x1) * 0.5f;
            bx1 = (y0 + y1) * 0.5f;
            bx2 = x1 - x0;
            bx3 = y1 - y0;
        }
        *(float4*)(g_boxes + nq * 4) = make_float4(bx0, bx1, bx2, bx3);
    }
}

// ---------------------------------------------------------------------------
// Kernel 2 (fused): offsets+attn projections, sampling locations,
// point-in-mask, per-head softmax.
// grid = 150 blocks (16 queries each), 256 threads.
// Phase A: GEMM (thread = output column, 16 queries)
// Phase B: pts   (thread = sample s, warp = head; loop over 16 queries)
// ---------------------------------------------------------------------------
__global__ __launch_bounds__(256) void kprojpts(const float* __restrict__ query,
                                                const float* __restrict__ Woff,
                                                const float* __restrict__ boff,
                                                const float* __restrict__ Wattn,
                                                const float* __restrict__ battn)
{
    __shared__ float sm[16 * 768];     // 48 KB: queries, then projection results
    int tid = threadIdx.x;
    int q0  = blockIdx.x * 16;

    // load 16 query rows into sm[0 : 4096]
    for (int i = tid; i < 16 * 256; i += 256)
        sm[i] = query[(size_t)q0 * 256 + i];
    __syncthreads();

    float acc0[16], acc1[16], acc2[16];
    #pragma unroll
    for (int i = 0; i < 16; ++i) { acc0[i] = 0.f; acc1[i] = 0.f; acc2[i] = 0.f; }

    float w0 = Woff[tid];
    float w1 = Woff[256 + tid];
    float w2 = Wattn[tid];
    #pragma unroll 2
    for (int k = 0; k < 256; ++k) {
        float nw0 = 0.f, nw1 = 0.f, nw2 = 0.f;
        if (k < 255) {
            nw0 = Woff[(size_t)(k + 1) * 512 + tid];
            nw1 = Woff[(size_t)(k + 1) * 512 + 256 + tid];
            nw2 = Wattn[(size_t)(k + 1) * 256 + tid];
        }
        #pragma unroll
        for (int i = 0; i < 16; ++i) {
            float qv = sm[i * 256 + k];
            acc0[i] = fmaf(qv, w0, acc0[i]);
            acc1[i] = fmaf(qv, w1, acc1[i]);
            acc2[i] = fmaf(qv, w2, acc2[i]);
        }
        w0 = nw0; w1 = nw1; w2 = nw2;
    }
    __syncthreads();   // done reading queries from sm

    float b0 = boff[tid], b1 = boff[256 + tid], b2 = battn[tid];
    #pragma unroll
    for (int i = 0; i < 16; ++i) {
        float* row = sm + i * 768;
        row[tid]       = acc0[i] + b0;
        row[256 + tid] = acc1[i] + b1;
        row[512 + tid] = acc2[i] + b2;
    }
    __syncthreads();

    // Phase B: thread tid = sample s (head = s>>5 = warp id)
    int s = tid;
    for (int qi = 0; qi < 16; ++qi) {
        int nq = q0 + qi;
        float4 bx = *(const float4*)(g_boxes + nq * 4);
        float ox = sm[qi * 768 + 2 * s];
        float oy = sm[qi * 768 + 2 * s + 1];
        float at = sm[qi * 768 + 512 + s];

        // loc = ctr + off/NPTS * wh * 0.5 == ctr + off * wh/16
        float lx = bx.x + ox * (bx.z * 0.0625f);
        float ly = bx.y + oy * (bx.w * 0.0625f);

        // point-in-mask: trunc-toward-zero then clamp
        int px = (int)(lx * 128.0f); px = min(max(px, 0), 127);
        int py = (int)(ly * 128.0f); py = min(max(py, 0), 127);
        unsigned bit = (g_packed[(size_t)nq * 512 + py * 4 + (px >> 5)] >> (px & 31)) & 1u;

        float e = at * (float)bit;

        float mx = e;
        #pragma unroll
        for (int o = 16; o > 0; o >>= 1) mx = fmaxf(mx, __shfl_xor_sync(0xffffffffu, mx, o));
        float ex = expf(e - mx);
        float smv = ex;
        #pragma unroll
        for (int o = 16; o > 0; o >>= 1) smv += __shfl_xor_sync(0xffffffffu, smv, o);
        float w = ex / smv;

        ((float2*)(g_locs + (size_t)nq * 512))[s] = make_float2(lx, ly);
        g_wts[(size_t)nq * 256 + s] = w;
    }
}

// ---------------------------------------------------------------------------
// Kernel 3 (hot): bilinear gather + weighted aggregation of full input rows
// grid = NQ blocks, 8 warps (warp = head). Lane owns 8 channels.
// ---------------------------------------------------------------------------
__global__ __launch_bounds__(256) void ksamp(const float* __restrict__ input)
{
    int nq   = blockIdx.x;
    int n    = nq / LQ;
    int warp = threadIdx.x >> 5;
    int lane = threadIdx.x & 31;

    const float* base = input + (size_t)n * (LEN_IN * C_DIM);

    float2 L = ((const float2*)(g_locs + (size_t)nq * 512))[warp * 32 + lane];
    float  Wt = g_wts[(size_t)nq * 256 + warp * 32 + lane];
    float  Lx = L.x, Ly = L.y;

    float acc[8] = {0.f, 0.f, 0.f, 0.f, 0.f, 0.f, 0.f, 0.f};
    float bacc = 0.f;

#define CORNER(XI, YI, CWV)                                                     \
    do {                                                                        \
        int _x = (XI), _y = (YI);                                               \
        if (_x >= 0 && _x < Wl && _y >= 0 && _y < Wl) {                         \
            float _cw = (CWV);                                                  \
            const float4* _r = (const float4*)(baseL +                          \
                               (size_t)(_y * Wl + _x) * C_DIM);                 \
            float4 _v0 = _r[lane];                                              \
            float4 _v1 = _r[32 + lane];                                         \
            acc[0] = fmaf(_cw, _v0.x, acc[0]);                                  \
            acc[1] = fmaf(_cw, _v0.y, acc[1]);                                  \
            acc[2] = fmaf(_cw, _v0.z, acc[2]);                                  \
            acc[3] = fmaf(_cw, _v0.w, acc[3]);                                  \
            acc[4] = fmaf(_cw, _v1.x, acc[4]);                                  \
            acc[5] = fmaf(_cw, _v1.y, acc[5]);                                  \
            acc[6] = fmaf(_cw, _v1.z, acc[6]);                                  \
            acc[7] = fmaf(_cw, _v1.w, acc[7]);                                  \
            bacc += _cw;                                                        \
        }                                                                       \
    } while (0)

    #pragma unroll
    for (int l = 0; l < 4; ++l) {
        const int Wl     = 128 >> l;
        const int startl = (l == 0) ? 0 : (l == 1) ? 16384 : (l == 2) ? 20480 : 21504;
        const float fW   = (float)Wl;
        const float* baseL = base + (size_t)startl * C_DIM;
        #pragma unroll
        for (int p = 0; p < 8; ++p) {
            int s = l * 8 + p;
            float lx = __shfl_sync(0xffffffffu, Lx, s);
            float ly = __shfl_sync(0xffffffffu, Ly, s);
            float wt = __shfl_sync(0xffffffffu, Wt, s);

            float px = lx * fW - 0.5f;
            float py = ly * fW - 0.5f;
            float xf = floorf(px), yf = floorf(py);
            float fx = px - xf,    fy = py - yf;
            int   x0 = (int)xf,    y0 = (int)yf;
            float gx = 1.0f - fx,  gy = 1.0f - fy;

            CORNER(x0,     y0,     wt * gx * gy);
            CORNER(x0 + 1, y0,     wt * fx * gy);
            CORNER(x0,     y0 + 1, wt * gx * fy);
            CORNER(x0 + 1, y0 + 1, wt * fx * fy);
        }
    }
#undef CORNER

    float* ap = g_agg + ((size_t)nq * 8 + warp) * 256;
    ((float4*)ap)[lane]      = make_float4(acc[0], acc[1], acc[2], acc[3]);
    ((float4*)ap)[32 + lane] = make_float4(acc[4], acc[5], acc[6], acc[7]);
    if (lane == 0)
        g_beta[nq * 8 + warp] = bacc;
}

// ---------------------------------------------------------------------------
// Kernel 4: per-head value projection
// out_core[q, 32h+d] = agg_h . Wval[:, 32h+d] + beta * b_val[32h+d]
// grid = (150, 8): 16 queries x head h, 256 threads
// ---------------------------------------------------------------------------
__global__ __launch_bounds__(256) void khead(const float* __restrict__ Wval,
                                             const float* __restrict__ bval)
{
    __shared__ float as[16 * 256];   // agg tile
    __shared__ float ws[256 * 32];   // Wval head slice

    int h   = blockIdx.y;
    int q0  = blockIdx.x * 16;
    int tid = threadIdx.x;

    for (int i = tid; i < 16 * 256; i += 256) {
        int qi = i >> 8, c = i & 255;
        as[i] = g_agg[((size_t)(q0 + qi) * 8 + h) * 256 + c];
    }
    for (int i = tid; i < 256 * 32; i += 256) {
        int c = i >> 5, d = i & 31;
        ws[i] = Wval[(size_t)c * 256 + h * 32 + d];
    }
    __syncthreads();

    int d  = tid & 31;
    int qg = tid >> 5;                  // queries qg and qg+8

    float a0 = 0.f, a1 = 0.f;
    for (int c = 0; c < 256; ++c) {
        float w = ws[c * 32 + d];
        a0 = fmaf(as[qg * 256 + c],       w, a0);
        a1 = fmaf(as[(qg + 8) * 256 + c], w, a1);
    }
    float bv = bval[h * 32 + d];
    int od = h * 32 + d;
    g_outcore[(size_t)(q0 + qg) * 256 + od]     = a0 + g_beta[(q0 + qg) * 8 + h] * bv;
    g_outcore[(size_t)(q0 + qg + 8) * 256 + od] = a1 + g_beta[(q0 + qg + 8) * 8 + h] * bv;
}

// ---------------------------------------------------------------------------
// Kernel 5: output projection  out = out_core @ W_out + b_out
// grid = 150 blocks (16 queries), 256 threads
// ---------------------------------------------------------------------------
__global__ __launch_bounds__(256) void kout(const float* __restrict__ Wout,
                                            const float* __restrict__ bout,
                                            float* __restrict__ out)
{
    __shared__ float xs[16 * 256];
    int q0  = blockIdx.x * 16;
    int tid = threadIdx.x;

    for (int i = tid; i < 16 * 256; i += 256)
        xs[i] = g_outcore[(size_t)q0 * 256 + i];
    __syncthreads();

    float acc[16];
    #pragma unroll
    for (int i = 0; i < 16; ++i) acc[i] = 0.f;

    float w = Wout[tid];
    #pragma unroll 2
    for (int k = 0; k < 256; ++k) {
        float nw = 0.f;
        if (k < 255) nw = Wout[(size_t)(k + 1) * 256 + tid];
        #pragma unroll
        for (int i = 0; i < 16; ++i)
            acc[i] = fmaf(xs[i * 256 + k], w, acc[i]);
        w = nw;
    }
    float b = bout[tid];
    #pragma unroll
    for (int i = 0; i < 16; ++i)
        out[(size_t)(q0 + i) * 256 + tid] = acc[i] + b;
}

// ---------------------------------------------------------------------------
// Launch
// ---------------------------------------------------------------------------
extern "C" void kernel_launch(void* const* d_in, const int* in_sizes, int n_in,
                              void* d_out, int out_size)
{
    const float* query = (const float*)d_in[0];
    // d_in[1] reference_bboxs : unused by reference
    const float* masks = (const float*)d_in[2];
    // d_in[3] mask_threshold  : unused (reference uses > 0)
    const float* input = (const float*)d_in[4];
    // d_in[5] spatial_shapes, d_in[6] level_start_index : hardcoded
    // d_in[7] padding_mask    : structurally all-false
    const float* Woff  = (const float*)d_in[8];
    const float* boff  = (const float*)d_in[9];
    const float* Wattn = (const float*)d_in[10];
    const float* battn = (const float*)d_in[11];
    const float* Wval  = (const float*)d_in[12];
    const float* bval  = (const float*)d_in[13];
    const float* Wout  = (const float*)d_in[14];
    const float* bout  = (const float*)d_in[15];
    float* out = (float*)d_out;

    kbox    <<<NQ, 256>>>(masks);
    kprojpts<<<150, 256>>>(query, Woff, boff, Wattn, battn);
    ksamp   <<<NQ, 256>>>(input);
    khead   <<<dim3(150, 8), 256>>>(Wval, bval);
    kout    <<<150, 256>>>(Wout, bout, out);
}

// round 13
// speedup vs baseline: 1.0070x; 1.0070x over previous
#include <cuda_runtime.h>
#include <cstdint>

// ---------------------------------------------------------------------------
// Problem constants (hardcoded from the reference)
// ---------------------------------------------------------------------------
#define N_B    8
#define LQ     300
#define NQ     2400        // N_B * LQ
#define C_DIM  256
#define HEADS  8
#define NLVL   4
#define NPTS   8
#define LEN_IN 21760
// level starts: 0, 16384, 20480, 21504  (sizes 128^2, 64^2, 32^2, 16^2)

// ---------------------------------------------------------------------------
// Scratch (device globals — no allocation allowed)
// ---------------------------------------------------------------------------
__device__ uint32_t g_packed[NQ * 512];          // 1-bit mask per (n,q): 128x128 bits
__device__ float    g_boxes[NQ * 4];             // cx, cy, w, h
__device__ float    g_locs[NQ * 512];            // 256 points * (x,y)
__device__ float    g_wts[NQ * 256];             // softmaxed weights
__device__ float    g_agg[NQ * 8 * 256];         // per (n,q,head): aggregated 256-vec
__device__ float    g_beta[NQ * 8];              // per (n,q,head): sum of valid corner weights
__device__ float    g_outcore[NQ * 256];         // pre-output-projection

// ---------------------------------------------------------------------------
// Kernel 1: bounding boxes + packed binary masks  (pure float4 streamer)
// grid = NQ blocks, 256 threads. Thread t handles 64 contiguous elements:
//   row = t>>1, half = t&1 (cols half*64 .. half*64+63)
// ---------------------------------------------------------------------------
__global__ __launch_bounds__(256) void kbox(const float* __restrict__ masks)
{
    int nq   = blockIdx.x;
    int tid  = threadIdx.x;
    int row  = tid >> 1;
    int half = tid & 1;

    __shared__ unsigned scol[4];   // per-x "any over y" bits (128 cols)
    __shared__ unsigned srow[4];   // per-y "any over x" bits (128 rows)
    if (tid < 4) { scol[tid] = 0u; srow[tid] = 0u; }
    __syncthreads();

    const float4* p = (const float4*)(masks + (size_t)nq * 16384 + tid * 64);

    unsigned w0 = 0u, w1 = 0u;
    #pragma unroll
    for (int j = 0; j < 8; ++j) {
        float4 v = p[j];
        unsigned b = (v.x > 0.0f ? 1u : 0u)
                   | (v.y > 0.0f ? 2u : 0u)
                   | (v.z > 0.0f ? 4u : 0u)
                   | (v.w > 0.0f ? 8u : 0u);
        w0 |= b << (j * 4);
    }
    #pragma unroll
    for (int j = 8; j < 16; ++j) {
        float4 v = p[j];
        unsigned b = (v.x > 0.0f ? 1u : 0u)
                   | (v.y > 0.0f ? 2u : 0u)
                   | (v.z > 0.0f ? 4u : 0u)
                   | (v.w > 0.0f ? 8u : 0u);
        w1 |= b << ((j - 8) * 4);
    }

    // packed mask store (coalesced: warp covers 256 contiguous bytes)
    uint32_t* pk = g_packed + (size_t)nq * 512 + row * 4 + half * 2;
    pk[0] = w0;
    pk[1] = w1;

    // column-any reduction
    if (w0) atomicOr(&scol[half * 2], w0);
    if (w1) atomicOr(&scol[half * 2 + 1], w1);

    // row-any: combine the two halves of this row (adjacent lanes)
    unsigned any = (w0 | w1) ? 1u : 0u;
    unsigned both = any | __shfl_xor_sync(0xffffffffu, any, 1);
    if (half == 0 && both)
        atomicOr(&srow[row >> 5], 1u << (row & 31));
    __syncthreads();

    if (tid == 0) {
        unsigned anyc = scol[0] | scol[1] | scol[2] | scol[3];
        float bx0 = 0.f, bx1 = 0.f, bx2 = 0.f, bx3 = 0.f;
        if (anyc) {
            int xmin = 0, xmax = 0, ymin = 0, ymax = 0;
            #pragma unroll
            for (int i = 3; i >= 0; --i) if (scol[i]) xmin = i * 32 + __ffs((int)scol[i]) - 1;
            #pragma unroll
            for (int i = 0; i < 4; ++i)  if (scol[i]) xmax = i * 32 + 31 - __clz((int)scol[i]);
            #pragma unroll
            for (int i = 3; i >= 0; --i) if (srow[i]) ymin = i * 32 + __ffs((int)srow[i]) - 1;
            #pragma unroll
            for (int i = 0; i < 4; ++i)  if (srow[i]) ymax = i * 32 + 31 - __clz((int)srow[i]);
            float x0 = xmin * (1.0f / 128.0f), x1 = (xmax + 1) * (1.0f / 128.0f);
            float y0 = ymin * (1.0f / 128.0f), y1 = (ymax + 1) * (1.0f / 128.0f);
            bx0 = (x0 + x1) * 0.5f;
            bx1 = (y0 + y1) * 0.5f;
            bx2 = x1 - x0;
            bx3 = y1 - y0;
        }
        *(float4*)(g_boxes + nq * 4) = make_float4(bx0, bx1, bx2, bx3);
    }
}

// ---------------------------------------------------------------------------
// Kernel 2 (fused): offsets+attn projections, sampling locations,
// point-in-mask, per-head softmax.
// grid = 150 blocks (16 queries each), 256 threads.
// Phase A: GEMM (thread = output column, 16 queries)
// Phase B: pts   (thread = sample s, warp = head; loop over 16 queries)
// ---------------------------------------------------------------------------
__global__ __launch_bounds__(256) void kprojpts(const float* __restrict__ query,
                                                const float* __restrict__ Woff,
                                                const float* __restrict__ boff,
                                                const float* __restrict__ Wattn,
                                                const float* __restrict__ battn)
{
    __shared__ float sm[16 * 768];     // 48 KB: queries, then projection results
    int tid = threadIdx.x;
    int q0  = blockIdx.x * 16;

    // load 16 query rows into sm[0 : 4096]
    for (int i = tid; i < 16 * 256; i += 256)
        sm[i] = query[(size_t)q0 * 256 + i];
    __syncthreads();

    float acc0[16], acc1[16], acc2[16];
    #pragma unroll
    for (int i = 0; i < 16; ++i) { acc0[i] = 0.f; acc1[i] = 0.f; acc2[i] = 0.f; }

    float w0 = Woff[tid];
    float w1 = Woff[256 + tid];
    float w2 = Wattn[tid];
    #pragma unroll 2
    for (int k = 0; k < 256; ++k) {
        float nw0 = 0.f, nw1 = 0.f, nw2 = 0.f;
        if (k < 255) {
            nw0 = Woff[(size_t)(k + 1) * 512 + tid];
            nw1 = Woff[(size_t)(k + 1) * 512 + 256 + tid];
            nw2 = Wattn[(size_t)(k + 1) * 256 + tid];
        }
        #pragma unroll
        for (int i = 0; i < 16; ++i) {
            float qv = sm[i * 256 + k];
            acc0[i] = fmaf(qv, w0, acc0[i]);
            acc1[i] = fmaf(qv, w1, acc1[i]);
            acc2[i] = fmaf(qv, w2, acc2[i]);
        }
        w0 = nw0; w1 = nw1; w2 = nw2;
    }
    __syncthreads();   // done reading queries from sm

    float b0 = boff[tid], b1 = boff[256 + tid], b2 = battn[tid];
    #pragma unroll
    for (int i = 0; i < 16; ++i) {
        float* row = sm + i * 768;
        row[tid]       = acc0[i] + b0;
        row[256 + tid] = acc1[i] + b1;
        row[512 + tid] = acc2[i] + b2;
    }
    __syncthreads();

    // Phase B: thread tid = sample s (head = s>>5 = warp id)
    int s = tid;
    for (int qi = 0; qi < 16; ++qi) {
        int nq = q0 + qi;
        float4 bx = *(const float4*)(g_boxes + nq * 4);
        float ox = sm[qi * 768 + 2 * s];
        float oy = sm[qi * 768 + 2 * s + 1];
        float at = sm[qi * 768 + 512 + s];

        // loc = ctr + off/NPTS * wh * 0.5 == ctr + off * wh/16
        float lx = bx.x + ox * (bx.z * 0.0625f);
        float ly = bx.y + oy * (bx.w * 0.0625f);

        // point-in-mask: trunc-toward-zero then clamp
        int px = (int)(lx * 128.0f); px = min(max(px, 0), 127);
        int py = (int)(ly * 128.0f); py = min(max(py, 0), 127);
        unsigned bit = (g_packed[(size_t)nq * 512 + py * 4 + (px >> 5)] >> (px & 31)) & 1u;

        float e = at * (float)bit;

        float mx = e;
        #pragma unroll
        for (int o = 16; o > 0; o >>= 1) mx = fmaxf(mx, __shfl_xor_sync(0xffffffffu, mx, o));
        float ex = expf(e - mx);
        float smv = ex;
        #pragma unroll
        for (int o = 16; o > 0; o >>= 1) smv += __shfl_xor_sync(0xffffffffu, smv, o);
        float w = ex / smv;

        ((float2*)(g_locs + (size_t)nq * 512))[s] = make_float2(lx, ly);
        g_wts[(size_t)nq * 256 + s] = w;
    }
}

// ---------------------------------------------------------------------------
// Kernel 3 (hot): bilinear gather + weighted aggregation of full input rows
// grid = NQ blocks, 8 warps (warp = head). Lane owns 8 channels.
// ---------------------------------------------------------------------------
__global__ __launch_bounds__(256) void ksamp(const float* __restrict__ input)
{
    int nq   = blockIdx.x;
    int n    = nq / LQ;
    int warp = threadIdx.x >> 5;
    int lane = threadIdx.x & 31;

    const float* base = input + (size_t)n * (LEN_IN * C_DIM);

    float2 L = ((const float2*)(g_locs + (size_t)nq * 512))[warp * 32 + lane];
    float  Wt = g_wts[(size_t)nq * 256 + warp * 32 + lane];
    float  Lx = L.x, Ly = L.y;

    float acc[8] = {0.f, 0.f, 0.f, 0.f, 0.f, 0.f, 0.f, 0.f};
    float bacc = 0.f;

#define CORNER(XI, YI, CWV)                                                     \
    do {                                                                        \
        int _x = (XI), _y = (YI);                                               \
        if (_x >= 0 && _x < Wl && _y >= 0 && _y < Wl) {                         \
            float _cw = (CWV);                                                  \
            const float4* _r = (const float4*)(baseL +                          \
                               (size_t)(_y * Wl + _x) * C_DIM);                 \
            float4 _v0 = _r[lane];                                              \
            float4 _v1 = _r[32 + lane];                                         \
            acc[0] = fmaf(_cw, _v0.x, acc[0]);                                  \
            acc[1] = fmaf(_cw, _v0.y, acc[1]);                                  \
            acc[2] = fmaf(_cw, _v0.z, acc[2]);                                  \
            acc[3] = fmaf(_cw, _v0.w, acc[3]);                                  \
            acc[4] = fmaf(_cw, _v1.x, acc[4]);                                  \
            acc[5] = fmaf(_cw, _v1.y, acc[5]);                                  \
            acc[6] = fmaf(_cw, _v1.z, acc[6]);                                  \
            acc[7] = fmaf(_cw, _v1.w, acc[7]);                                  \
            bacc += _cw;                                                        \
        }                                                                       \
    } while (0)

    #pragma unroll
    for (int l = 0; l < 4; ++l) {
        const int Wl     = 128 >> l;
        const int startl = (l == 0) ? 0 : (l == 1) ? 16384 : (l == 2) ? 20480 : 21504;
        const float fW   = (float)Wl;
        const float* baseL = base + (size_t)startl * C_DIM;
        #pragma unroll
        for (int p = 0; p < 8; ++p) {
            int s = l * 8 + p;
            float lx = __shfl_sync(0xffffffffu, Lx, s);
            float ly = __shfl_sync(0xffffffffu, Ly, s);
            float wt = __shfl_sync(0xffffffffu, Wt, s);

            float px = lx * fW - 0.5f;
            float py = ly * fW - 0.5f;
            float xf = floorf(px), yf = floorf(py);
            float fx = px - xf,    fy = py - yf;
            int   x0 = (int)xf,    y0 = (int)yf;
            float gx = 1.0f - fx,  gy = 1.0f - fy;

            CORNER(x0,     y0,     wt * gx * gy);
            CORNER(x0 + 1, y0,     wt * fx * gy);
            CORNER(x0,     y0 + 1, wt * gx * fy);
            CORNER(x0 + 1, y0 + 1, wt * fx * fy);
        }
    }
#undef CORNER

    float* ap = g_agg + ((size_t)nq * 8 + warp) * 256;
    ((float4*)ap)[lane]      = make_float4(acc[0], acc[1], acc[2], acc[3]);
    ((float4*)ap)[32 + lane] = make_float4(acc[4], acc[5], acc[6], acc[7]);
    if (lane == 0)
        g_beta[nq * 8 + warp] = bacc;
}

// ---------------------------------------------------------------------------
// Kernel 4: per-head value projection
// out_core[q, 32h+d] = agg_h . Wval[:, 32h+d] + beta * b_val[32h+d]
// grid = (150, 8): 16 queries x head h, 256 threads
// ---------------------------------------------------------------------------
__global__ __launch_bounds__(256) void khead(const float* __restrict__ Wval,
                                             const float* __restrict__ bval)
{
    __shared__ float as[16 * 256];   // agg tile
    __shared__ float ws[256 * 32];   // Wval head slice

    int h   = blockIdx.y;
    int q0  = blockIdx.x * 16;
    int tid = threadIdx.x;

    for (int i = tid; i < 16 * 256; i += 256) {
        int qi = i >> 8, c = i & 255;
        as[i] = g_agg[((size_t)(q0 + qi) * 8 + h) * 256 + c];
    }
    for (int i = tid; i < 256 * 32; i += 256) {
        int c = i >> 5, d = i & 31;
        ws[i] = Wval[(size_t)c * 256 + h * 32 + d];
    }
    __syncthreads();

    int d  = tid & 31;
    int qg = tid >> 5;                  // queries qg and qg+8

    float a0 = 0.f, a1 = 0.f;
    for (int c = 0; c < 256; ++c) {
        float w = ws[c * 32 + d];
        a0 = fmaf(as[qg * 256 + c],       w, a0);
        a1 = fmaf(as[(qg + 8) * 256 + c], w, a1);
    }
    float bv = bval[h * 32 + d];
    int od = h * 32 + d;
    g_outcore[(size_t)(q0 + qg) * 256 + od]     = a0 + g_beta[(q0 + qg) * 8 + h] * bv;
    g_outcore[(size_t)(q0 + qg + 8) * 256 + od] = a1 + g_beta[(q0 + qg + 8) * 8 + h] * bv;
}

// ---------------------------------------------------------------------------
// Kernel 5: output projection  out = out_core @ W_out + b_out
// grid = 150 blocks (16 queries), 256 threads
// ---------------------------------------------------------------------------
__global__ __launch_bounds__(256) void kout(const float* __restrict__ Wout,
                                            const float* __restrict__ bout,
                                            float* __restrict__ out)
{
    __shared__ float xs[16 * 256];
    int q0  = blockIdx.x * 16;
    int tid = threadIdx.x;

    for (int i = tid; i < 16 * 256; i += 256)
        xs[i] = g_outcore[(size_t)q0 * 256 + i];
    __syncthreads();

    float acc[16];
    #pragma unroll
    for (int i = 0; i < 16; ++i) acc[i] = 0.f;

    float w = Wout[tid];
    #pragma unroll 2
    for (int k = 0; k < 256; ++k) {
        float nw = 0.f;
        if (k < 255) nw = Wout[(size_t)(k + 1) * 256 + tid];
        #pragma unroll
        for (int i = 0; i < 16; ++i)
            acc[i] = fmaf(xs[i * 256 + k], w, acc[i]);
        w = nw;
    }
    float b = bout[tid];
    #pragma unroll
    for (int i = 0; i < 16; ++i)
        out[(size_t)(q0 + i) * 256 + tid] = acc[i] + b;
}

// ---------------------------------------------------------------------------
// Launch
// ---------------------------------------------------------------------------
extern "C" void kernel_launch(void* const* d_in, const int* in_sizes, int n_in,
                              void* d_out, int out_size)
{
    const float* query = (const float*)d_in[0];
    // d_in[1] reference_bboxs : unused by reference
    const float* masks = (const float*)d_in[2];
    // d_in[3] mask_threshold  : unused (reference uses > 0)
    const float* input = (const float*)d_in[4];
    // d_in[5] spatial_shapes, d_in[6] level_start_index : hardcoded
    // d_in[7] padding_mask    : structurally all-false
    const float* Woff  = (const float*)d_in[8];
    const float* boff  = (const float*)d_in[9];
    const float* Wattn = (const float*)d_in[10];
    const float* battn = (const float*)d_in[11];
    const float* Wval  = (const float*)d_in[12];
    const float* bval  = (const float*)d_in[13];
    const float* Wout  = (const float*)d_in[14];
    const float* bout  = (const float*)d_in[15];
    float* out = (float*)d_out;

    kbox    <<<NQ, 256>>>(masks);
    kprojpts<<<150, 256>>>(query, Woff, boff, Wattn, battn);
    ksamp   <<<NQ, 256>>>(input);
    khead   <<<dim3(150, 8), 256>>>(Wval, bval);
    kout    <<<150, 256>>>(Wout, bout, out);
}

// round 14
// speedup vs baseline: 1.0072x; 1.0003x over previous
#include <cuda_runtime.h>
#include <cstdint>

// ---------------------------------------------------------------------------
// Problem constants (hardcoded from the reference)
// ---------------------------------------------------------------------------
#define N_B    8
#define LQ     300
#define NQ     2400        // N_B * LQ
#define C_DIM  256
#define HEADS  8
#define NLVL   4
#define NPTS   8
#define LEN_IN 21760
// level starts: 0, 16384, 20480, 21504  (sizes 128^2, 64^2, 32^2, 16^2)

// ---------------------------------------------------------------------------
// Scratch (device globals — no allocation allowed)
// ---------------------------------------------------------------------------
__device__ uint32_t g_packed[NQ * 512];          // 1-bit mask per (n,q): 128x128 bits
__device__ float    g_boxes[NQ * 4];             // cx, cy, w, h
__device__ float    g_locs[NQ * 512];            // 256 points * (x,y)
__device__ float    g_wts[NQ * 256];             // softmaxed weights
__device__ float    g_agg[NQ * 8 * 256];         // per (n,q,head): aggregated 256-vec
__device__ float    g_beta[NQ * 8];              // per (n,q,head): sum of valid corner weights
__device__ float    g_outcore[NQ * 256];         // pre-output-projection

// ---------------------------------------------------------------------------
// Kernel 1: bounding boxes + packed binary masks  (pure float4 streamer)
// grid = NQ blocks, 256 threads. Thread t handles 64 contiguous elements:
//   row = t>>1, half = t&1 (cols half*64 .. half*64+63)
// ---------------------------------------------------------------------------
__global__ __launch_bounds__(256) void kbox(const float* __restrict__ masks)
{
    int nq   = blockIdx.x;
    int tid  = threadIdx.x;
    int row  = tid >> 1;
    int half = tid & 1;

    __shared__ unsigned scol[4];   // per-x "any over y" bits (128 cols)
    __shared__ unsigned srow[4];   // per-y "any over x" bits (128 rows)
    if (tid < 4) { scol[tid] = 0u; srow[tid] = 0u; }
    __syncthreads();

    const float4* p = (const float4*)(masks + (size_t)nq * 16384 + tid * 64);

    unsigned w0 = 0u, w1 = 0u;
    #pragma unroll
    for (int j = 0; j < 8; ++j) {
        float4 v = p[j];
        unsigned b = (v.x > 0.0f ? 1u : 0u)
                   | (v.y > 0.0f ? 2u : 0u)
                   | (v.z > 0.0f ? 4u : 0u)
                   | (v.w > 0.0f ? 8u : 0u);
        w0 |= b << (j * 4);
    }
    #pragma unroll
    for (int j = 8; j < 16; ++j) {
        float4 v = p[j];
        unsigned b = (v.x > 0.0f ? 1u : 0u)
                   | (v.y > 0.0f ? 2u : 0u)
                   | (v.z > 0.0f ? 4u : 0u)
                   | (v.w > 0.0f ? 8u : 0u);
        w1 |= b << ((j - 8) * 4);
    }

    // packed mask store (coalesced: warp covers 256 contiguous bytes)
    uint32_t* pk = g_packed + (size_t)nq * 512 + row * 4 + half * 2;
    pk[0] = w0;
    pk[1] = w1;

    // column-any reduction
    if (w0) atomicOr(&scol[half * 2], w0);
    if (w1) atomicOr(&scol[half * 2 + 1], w1);

    // row-any: combine the two halves of this row (adjacent lanes)
    unsigned any = (w0 | w1) ? 1u : 0u;
    unsigned both = any | __shfl_xor_sync(0xffffffffu, any, 1);
    if (half == 0 && both)
        atomicOr(&srow[row >> 5], 1u << (row & 31));
    __syncthreads();

    if (tid == 0) {
        unsigned anyc = scol[0] | scol[1] | scol[2] | scol[3];
        float bx0 = 0.f, bx1 = 0.f, bx2 = 0.f, bx3 = 0.f;
        if (anyc) {
            int xmin = 0, xmax = 0, ymin = 0, ymax = 0;
            #pragma unroll
            for (int i = 3; i >= 0; --i) if (scol[i]) xmin = i * 32 + __ffs((int)scol[i]) - 1;
            #pragma unroll
            for (int i = 0; i < 4; ++i)  if (scol[i]) xmax = i * 32 + 31 - __clz((int)scol[i]);
            #pragma unroll
            for (int i = 3; i >= 0; --i) if (srow[i]) ymin = i * 32 + __ffs((int)srow[i]) - 1;
            #pragma unroll
            for (int i = 0; i < 4; ++i)  if (srow[i]) ymax = i * 32 + 31 - __clz((int)srow[i]);
            float x0 = xmin * (1.0f / 128.0f), x1 = (xmax + 1) * (1.0f / 128.0f);
            float y0 = ymin * (1.0f / 128.0f), y1 = (ymax + 1) * (1.0f / 128.0f);
            bx0 = (x0 + x1) * 0.5f;
            bx1 = (y0 + y1) * 0.5f;
            bx2 = x1 - x0;
            bx3 = y1 - y0;
        }
        *(float4*)(g_boxes + nq * 4) = make_float4(bx0, bx1, bx2, bx3);
    }
}

// ---------------------------------------------------------------------------
// Kernel 2 (fused): offsets+attn projections, sampling locations,
// point-in-mask, per-head softmax.
// grid = 150 blocks (16 queries each), 256 threads.
// Phase A: GEMM (thread = output column, 16 queries)
// Phase B: pts   (thread = sample s, warp = head; loop over 16 queries)
// ---------------------------------------------------------------------------
__global__ __launch_bounds__(256) void kprojpts(const float* __restrict__ query,
                                                const float* __restrict__ Woff,
                                                const float* __restrict__ boff,
                                                const float* __restrict__ Wattn,
                                                const float* __restrict__ battn)
{
    __shared__ float sm[16 * 768];     // 48 KB: queries, then projection results
    int tid = threadIdx.x;
    int q0  = blockIdx.x * 16;

    // load 16 query rows into sm[0 : 4096]
    for (int i = tid; i < 16 * 256; i += 256)
        sm[i] = query[(size_t)q0 * 256 + i];
    __syncthreads();

    float acc0[16], acc1[16], acc2[16];
    #pragma unroll
    for (int i = 0; i < 16; ++i) { acc0[i] = 0.f; acc1[i] = 0.f; acc2[i] = 0.f; }

    float w0 = Woff[tid];
    float w1 = Woff[256 + tid];
    float w2 = Wattn[tid];
    #pragma unroll 2
    for (int k = 0; k < 256; ++k) {
        float nw0 = 0.f, nw1 = 0.f, nw2 = 0.f;
        if (k < 255) {
            nw0 = Woff[(size_t)(k + 1) * 512 + tid];
            nw1 = Woff[(size_t)(k + 1) * 512 + 256 + tid];
            nw2 = Wattn[(size_t)(k + 1) * 256 + tid];
        }
        #pragma unroll
        for (int i = 0; i < 16; ++i) {
            float qv = sm[i * 256 + k];
            acc0[i] = fmaf(qv, w0, acc0[i]);
            acc1[i] = fmaf(qv, w1, acc1[i]);
            acc2[i] = fmaf(qv, w2, acc2[i]);
        }
        w0 = nw0; w1 = nw1; w2 = nw2;
    }
    __syncthreads();   // done reading queries from sm

    float b0 = boff[tid], b1 = boff[256 + tid], b2 = battn[tid];
    #pragma unroll
    for (int i = 0; i < 16; ++i) {
        float* row = sm + i * 768;
        row[tid]       = acc0[i] + b0;
        row[256 + tid] = acc1[i] + b1;
        row[512 + tid] = acc2[i] + b2;
    }
    __syncthreads();

    // Phase B: thread tid = sample s (head = s>>5 = warp id)
    int s = tid;
    for (int qi = 0; qi < 16; ++qi) {
        int nq = q0 + qi;
        float4 bx = *(const float4*)(g_boxes + nq * 4);
        float ox = sm[qi * 768 + 2 * s];
        float oy = sm[qi * 768 + 2 * s + 1];
        float at = sm[qi * 768 + 512 + s];

        // loc = ctr + off/NPTS * wh * 0.5 == ctr + off * wh/16
        float lx = bx.x + ox * (bx.z * 0.0625f);
        float ly = bx.y + oy * (bx.w * 0.0625f);

        // point-in-mask: trunc-toward-zero then clamp
        int px = (int)(lx * 128.0f); px = min(max(px, 0), 127);
        int py = (int)(ly * 128.0f); py = min(max(py, 0), 127);
        unsigned bit = (g_packed[(size_t)nq * 512 + py * 4 + (px >> 5)] >> (px & 31)) & 1u;

        float e = at * (float)bit;

        float mx = e;
        #pragma unroll
        for (int o = 16; o > 0; o >>= 1) mx = fmaxf(mx, __shfl_xor_sync(0xffffffffu, mx, o));
        float ex = expf(e - mx);
        float smv = ex;
        #pragma unroll
        for (int o = 16; o > 0; o >>= 1) smv += __shfl_xor_sync(0xffffffffu, smv, o);
        float w = ex / smv;

        ((float2*)(g_locs + (size_t)nq * 512))[s] = make_float2(lx, ly);
        g_wts[(size_t)nq * 256 + s] = w;
    }
}

// ---------------------------------------------------------------------------
// Kernel 3 (hot): bilinear gather + weighted aggregation of full input rows
// grid = NQ blocks, 8 warps (warp = head). Lane owns 8 channels.
// ---------------------------------------------------------------------------
__global__ __launch_bounds__(256) void ksamp(const float* __restrict__ input)
{
    int nq   = blockIdx.x;
    int n    = nq / LQ;
    int warp = threadIdx.x >> 5;
    int lane = threadIdx.x & 31;

    const float* base = input + (size_t)n * (LEN_IN * C_DIM);

    float2 L = ((const float2*)(g_locs + (size_t)nq * 512))[warp * 32 + lane];
    float  Wt = g_wts[(size_t)nq * 256 + warp * 32 + lane];
    float  Lx = L.x, Ly = L.y;

    float acc[8] = {0.f, 0.f, 0.f, 0.f, 0.f, 0.f, 0.f, 0.f};
    float bacc = 0.f;

#define CORNER(XI, YI, CWV)                                                     \
    do {                                                                        \
        int _x = (XI), _y = (YI);                                               \
        if (_x >= 0 && _x < Wl && _y >= 0 && _y < Wl) {                         \
            float _cw = (CWV);                                                  \
            const float4* _r = (const float4*)(baseL +                          \
                               (size_t)(_y * Wl + _x) * C_DIM);                 \
            float4 _v0 = _r[lane];                                              \
            float4 _v1 = _r[32 + lane];                                         \
            acc[0] = fmaf(_cw, _v0.x, acc[0]);                                  \
            acc[1] = fmaf(_cw, _v0.y, acc[1]);                                  \
            acc[2] = fmaf(_cw, _v0.z, acc[2]);                                  \
            acc[3] = fmaf(_cw, _v0.w, acc[3]);                                  \
            acc[4] = fmaf(_cw, _v1.x, acc[4]);                                  \
            acc[5] = fmaf(_cw, _v1.y, acc[5]);                                  \
            acc[6] = fmaf(_cw, _v1.z, acc[6]);                                  \
            acc[7] = fmaf(_cw, _v1.w, acc[7]);                                  \
            bacc += _cw;                                                        \
        }                                                                       \
    } while (0)

    #pragma unroll
    for (int l = 0; l < 4; ++l) {
        const int Wl     = 128 >> l;
        const int startl = (l == 0) ? 0 : (l == 1) ? 16384 : (l == 2) ? 20480 : 21504;
        const float fW   = (float)Wl;
        const float* baseL = base + (size_t)startl * C_DIM;
        #pragma unroll
        for (int p = 0; p < 8; ++p) {
            int s = l * 8 + p;
            float lx = __shfl_sync(0xffffffffu, Lx, s);
            float ly = __shfl_sync(0xffffffffu, Ly, s);
            float wt = __shfl_sync(0xffffffffu, Wt, s);

            float px = lx * fW - 0.5f;
            float py = ly * fW - 0.5f;
            float xf = floorf(px), yf = floorf(py);
            float fx = px - xf,    fy = py - yf;
            int   x0 = (int)xf,    y0 = (int)yf;
            float gx = 1.0f - fx,  gy = 1.0f - fy;

            CORNER(x0,     y0,     wt * gx * gy);
            CORNER(x0 + 1, y0,     wt * fx * gy);
            CORNER(x0,     y0 + 1, wt * gx * fy);
            CORNER(x0 + 1, y0 + 1, wt * fx * fy);
        }
    }
#undef CORNER

    float* ap = g_agg + ((size_t)nq * 8 + warp) * 256;
    ((float4*)ap)[lane]      = make_float4(acc[0], acc[1], acc[2], acc[3]);
    ((float4*)ap)[32 + lane] = make_float4(acc[4], acc[5], acc[6], acc[7]);
    if (lane == 0)
        g_beta[nq * 8 + warp] = bacc;
}

// ---------------------------------------------------------------------------
// Kernel 4: per-head value projection
// out_core[q, 32h+d] = agg_h . Wval[:, 32h+d] + beta * b_val[32h+d]
// grid = (150, 8): 16 queries x head h, 256 threads
// ---------------------------------------------------------------------------
__global__ __launch_bounds__(256) void khead(const float* __restrict__ Wval,
                                             const float* __restrict__ bval)
{
    __shared__ float as[16 * 256];   // agg tile
    __shared__ float ws[256 * 32];   // Wval head slice

    int h   = blockIdx.y;
    int q0  = blockIdx.x * 16;
    int tid = threadIdx.x;

    for (int i = tid; i < 16 * 256; i += 256) {
        int qi = i >> 8, c = i & 255;
        as[i] = g_agg[((size_t)(q0 + qi) * 8 + h) * 256 + c];
    }
    for (int i = tid; i < 256 * 32; i += 256) {
        int c = i >> 5, d = i & 31;
        ws[i] = Wval[(size_t)c * 256 + h * 32 + d];
    }
    __syncthreads();

    int d  = tid & 31;
    int qg = tid >> 5;                  // queries qg and qg+8

    float a0 = 0.f, a1 = 0.f;
    for (int c = 0; c < 256; ++c) {
        float w = ws[c * 32 + d];
        a0 = fmaf(as[qg * 256 + c],       w, a0);
        a1 = fmaf(as[(qg + 8) * 256 + c], w, a1);
    }
    float bv = bval[h * 32 + d];
    int od = h * 32 + d;
    g_outcore[(size_t)(q0 + qg) * 256 + od]     = a0 + g_beta[(q0 + qg) * 8 + h] * bv;
    g_outcore[(size_t)(q0 + qg + 8) * 256 + od] = a1 + g_beta[(q0 + qg + 8) * 8 + h] * bv;
}

// ---------------------------------------------------------------------------
// Kernel 5: output projection  out = out_core @ W_out + b_out
// grid = 150 blocks (16 queries), 256 threads
// ---------------------------------------------------------------------------
__global__ __launch_bounds__(256) void kout(const float* __restrict__ Wout,
                                            const float* __restrict__ bout,
                                            float* __restrict__ out)
{
    __shared__ float xs[16 * 256];
    int q0  = blockIdx.x * 16;
    int tid = threadIdx.x;

    for (int i = tid; i < 16 * 256; i += 256)
        xs[i] = g_outcore[(size_t)q0 * 256 + i];
    __syncthreads();

    float acc[16];
    #pragma unroll
    for (int i = 0; i < 16; ++i) acc[i] = 0.f;

    float w = Wout[tid];
    #pragma unroll 2
    for (int k = 0; k < 256; ++k) {
        float nw = 0.f;
        if (k < 255) nw = Wout[(size_t)(k + 1) * 256 + tid];
        #pragma unroll
        for (int i = 0; i < 16; ++i)
            acc[i] = fmaf(xs[i * 256 + k], w, acc[i]);
        w = nw;
    }
    float b = bout[tid];
    #pragma unroll
    for (int i = 0; i < 16; ++i)
        out[(size_t)(q0 + i) * 256 + tid] = acc[i] + b;
}

// ---------------------------------------------------------------------------
// Launch
// ---------------------------------------------------------------------------
extern "C" void kernel_launch(void* const* d_in, const int* in_sizes, int n_in,
                              void* d_out, int out_size)
{
    const float* query = (const float*)d_in[0];
    // d_in[1] reference_bboxs : unused by reference
    const float* masks = (const float*)d_in[2];
    // d_in[3] mask_threshold  : unused (reference uses > 0)
    const float* input = (const float*)d_in[4];
    // d_in[5] spatial_shapes, d_in[6] level_start_index : hardcoded
    // d_in[7] padding_mask    : structurally all-false
    const float* Woff  = (const float*)d_in[8];
    const float* boff  = (const float*)d_in[9];
    const float* Wattn = (const float*)d_in[10];
    const float* battn = (const float*)d_in[11];
    const float* Wval  = (const float*)d_in[12];
    const float* bval  = (const float*)d_in[13];
    const float* Wout  = (const float*)d_in[14];
    const float* bout  = (const float*)d_in[15];
    float* out = (float*)d_out;

    kbox    <<<NQ, 256>>>(masks);
    kprojpts<<<150, 256>>>(query, Woff, boff, Wattn, battn);
    ksamp   <<<NQ, 256>>>(input);
    khead   <<<dim3(150, 8), 256>>>(Wval, bval);
    kout    <<<150, 256>>>(Wout, bout, out);
}

// round 15
// speedup vs baseline: 1.4414x; 1.4311x over previous
#include <cuda_runtime.h>
#include <cstdint>

// ---------------------------------------------------------------------------
// Problem constants (hardcoded from the reference)
// ---------------------------------------------------------------------------
#define N_B    8
#define LQ     300
#define NQ     2400        // N_B * LQ
#define C_DIM  256
#define HEADS  8
#define NLVL   4
#define NPTS   8
#define LEN_IN 21760
// level starts: 0, 16384, 20480, 21504  (sizes 128^2, 64^2, 32^2, 16^2)

// ---------------------------------------------------------------------------
// Scratch (device globals — no allocation allowed)
// ---------------------------------------------------------------------------
__device__ uint32_t g_packed[NQ * 512];          // 1-bit mask per (n,q): 128x128 bits
__device__ float    g_boxes[NQ * 4];             // cx, cy, w, h
__device__ float    g_locs[NQ * 512];            // 256 points * (x,y)
__device__ float    g_wts[NQ * 256];             // softmaxed weights
__device__ float    g_agg[NQ * 8 * 256];         // per (n,q,head): aggregated 256-vec
__device__ float    g_beta[NQ * 8];              // per (n,q,head): sum of valid corner weights
__device__ float    g_outcore[NQ * 256];         // pre-output-projection

// ---------------------------------------------------------------------------
// cp.async helpers
// ---------------------------------------------------------------------------
__device__ __forceinline__ uint32_t s2u(const void* p) {
    return (uint32_t)__cvta_generic_to_shared(p);
}
__device__ __forceinline__ void cp16(uint32_t dst, const void* src) {
    asm volatile("cp.async.cg.shared.global [%0], [%1], 16;" :: "r"(dst), "l"(src));
}
#define CP_COMMIT()  asm volatile("cp.async.commit_group;" ::: "memory")
#define CP_WAIT_1()  asm volatile("cp.async.wait_group 1;" ::: "memory")
#define CP_WAIT_0()  asm volatile("cp.async.wait_group 0;" ::: "memory")

// ---------------------------------------------------------------------------
// Kernel 1: bounding boxes + packed binary masks  (pure float4 streamer)
// grid = NQ blocks, 256 threads. Thread t handles 64 contiguous elements.
// ---------------------------------------------------------------------------
__global__ __launch_bounds__(256) void kbox(const float* __restrict__ masks)
{
    int nq   = blockIdx.x;
    int tid  = threadIdx.x;
    int row  = tid >> 1;
    int half = tid & 1;

    __shared__ unsigned scol[4];   // per-x "any over y" bits (128 cols)
    __shared__ unsigned srow[4];   // per-y "any over x" bits (128 rows)
    if (tid < 4) { scol[tid] = 0u; srow[tid] = 0u; }
    __syncthreads();

    const float4* p = (const float4*)(masks + (size_t)nq * 16384 + tid * 64);

    unsigned w0 = 0u, w1 = 0u;
    #pragma unroll
    for (int j = 0; j < 8; ++j) {
        float4 v = p[j];
        unsigned b = (v.x > 0.0f ? 1u : 0u)
                   | (v.y > 0.0f ? 2u : 0u)
                   | (v.z > 0.0f ? 4u : 0u)
                   | (v.w > 0.0f ? 8u : 0u);
        w0 |= b << (j * 4);
    }
    #pragma unroll
    for (int j = 8; j < 16; ++j) {
        float4 v = p[j];
        unsigned b = (v.x > 0.0f ? 1u : 0u)
                   | (v.y > 0.0f ? 2u : 0u)
                   | (v.z > 0.0f ? 4u : 0u)
                   | (v.w > 0.0f ? 8u : 0u);
        w1 |= b << ((j - 8) * 4);
    }

    uint32_t* pk = g_packed + (size_t)nq * 512 + row * 4 + half * 2;
    pk[0] = w0;
    pk[1] = w1;

    if (w0) atomicOr(&scol[half * 2], w0);
    if (w1) atomicOr(&scol[half * 2 + 1], w1);

    unsigned any = (w0 | w1) ? 1u : 0u;
    unsigned both = any | __shfl_xor_sync(0xffffffffu, any, 1);
    if (half == 0 && both)
        atomicOr(&srow[row >> 5], 1u << (row & 31));
    __syncthreads();

    if (tid == 0) {
        unsigned anyc = scol[0] | scol[1] | scol[2] | scol[3];
        float bx0 = 0.f, bx1 = 0.f, bx2 = 0.f, bx3 = 0.f;
        if (anyc) {
            int xmin = 0, xmax = 0, ymin = 0, ymax = 0;
            #pragma unroll
            for (int i = 3; i >= 0; --i) if (scol[i]) xmin = i * 32 + __ffs((int)scol[i]) - 1;
            #pragma unroll
            for (int i = 0; i < 4; ++i)  if (scol[i]) xmax = i * 32 + 31 - __clz((int)scol[i]);
            #pragma unroll
            for (int i = 3; i >= 0; --i) if (srow[i]) ymin = i * 32 + __ffs((int)srow[i]) - 1;
            #pragma unroll
            for (int i = 0; i < 4; ++i)  if (srow[i]) ymax = i * 32 + 31 - __clz((int)srow[i]);
            float x0 = xmin * (1.0f / 128.0f), x1 = (xmax + 1) * (1.0f / 128.0f);
            float y0 = ymin * (1.0f / 128.0f), y1 = (ymax + 1) * (1.0f / 128.0f);
            bx0 = (x0 + x1) * 0.5f;
            bx1 = (y0 + y1) * 0.5f;
            bx2 = x1 - x0;
            bx3 = y1 - y0;
        }
        *(float4*)(g_boxes + nq * 4) = make_float4(bx0, bx1, bx2, bx3);
    }
}

// ---------------------------------------------------------------------------
// Kernel 2 (fused): projections (cp.async double-buffered), locations,
// point-in-mask, per-head softmax.
// grid = 150 blocks (16 queries), 256 threads.
// dyn smem: qs[16*256] + 2 x wtile[16*768]   (112 KB)
// ---------------------------------------------------------------------------
__device__ __forceinline__ void stage_pp(const float* __restrict__ Woff,
                                         const float* __restrict__ Wattn,
                                         int k0, float* buf, int tid)
{
    #pragma unroll
    for (int j = 0; j < 12; ++j) {
        int idx = tid + j * 256;               // float4 index in tile, 0..3071
        int r   = idx / 192;                   // 192 float4 per row (512+256 floats)
        int c4  = idx - r * 192;
        const float* src = (c4 < 128)
            ? (Woff  + (size_t)(k0 + r) * 512 + c4 * 4)
            : (Wattn + (size_t)(k0 + r) * 256 + (c4 - 128) * 4);
        cp16(s2u(buf + r * 768 + c4 * 4), src);
    }
    CP_COMMIT();
}

__global__ __launch_bounds__(256) void kprojpts(const float* __restrict__ query,
                                                const float* __restrict__ Woff,
                                                const float* __restrict__ boff,
                                                const float* __restrict__ Wattn,
                                                const float* __restrict__ battn)
{
    extern __shared__ float sm[];
    float* qs  = sm;                 // 4096 floats
    float* wb0 = sm + 4096;          // 12288 floats
    float* wb1 = sm + 4096 + 12288;  // 12288 floats

    int tid = threadIdx.x;
    int q0  = blockIdx.x * 16;

    // issue first two weight tiles before anything else
    stage_pp(Woff, Wattn, 0,  wb0, tid);
    stage_pp(Woff, Wattn, 16, wb1, tid);

    for (int i = tid; i < 16 * 256; i += 256)
        qs[i] = query[(size_t)q0 * 256 + i];

    float acc0[16], acc1[16], acc2[16];
    #pragma unroll
    for (int i = 0; i < 16; ++i) { acc0[i] = 0.f; acc1[i] = 0.f; acc2[i] = 0.f; }

    for (int t = 0; t < 16; ++t) {
        if (t < 15) { CP_WAIT_1(); } else { CP_WAIT_0(); }
        __syncthreads();
        const float* buf = (t & 1) ? wb1 : wb0;
        #pragma unroll 4
        for (int r = 0; r < 16; ++r) {
            float w0 = buf[r * 768 + tid];
            float w1 = buf[r * 768 + 256 + tid];
            float w2 = buf[r * 768 + 512 + tid];
            int k = t * 16 + r;
            #pragma unroll
            for (int i = 0; i < 16; ++i) {
                float qv = qs[i * 256 + k];
                acc0[i] = fmaf(qv, w0, acc0[i]);
                acc1[i] = fmaf(qv, w1, acc1[i]);
                acc2[i] = fmaf(qv, w2, acc2[i]);
            }
        }
        __syncthreads();
        if (t + 2 < 16)
            stage_pp(Woff, Wattn, (t + 2) * 16, (t & 1) ? wb1 : wb0, tid);
    }

    // write projection results (+bias) into the wb0 region: res[16][768]
    float* res = wb0;
    {
        float b0 = boff[tid], b1 = boff[256 + tid], b2 = battn[tid];
        #pragma unroll
        for (int i = 0; i < 16; ++i) {
            res[i * 768 + tid]       = acc0[i] + b0;
            res[i * 768 + 256 + tid] = acc1[i] + b1;
            res[i * 768 + 512 + tid] = acc2[i] + b2;
        }
    }
    __syncthreads();

    // Phase B: thread tid = sample s (warp = head)
    int s = tid;
    for (int qi = 0; qi < 16; ++qi) {
        int nq = q0 + qi;
        float4 bx = *(const float4*)(g_boxes + nq * 4);
        float ox = res[qi * 768 + 2 * s];
        float oy = res[qi * 768 + 2 * s + 1];
        float at = res[qi * 768 + 512 + s];

        float lx = bx.x + ox * (bx.z * 0.0625f);
        float ly = bx.y + oy * (bx.w * 0.0625f);

        int px = (int)(lx * 128.0f); px = min(max(px, 0), 127);
        int py = (int)(ly * 128.0f); py = min(max(py, 0), 127);
        unsigned bit = (g_packed[(size_t)nq * 512 + py * 4 + (px >> 5)] >> (px & 31)) & 1u;

        float e = at * (float)bit;

        float mx = e;
        #pragma unroll
        for (int o = 16; o > 0; o >>= 1) mx = fmaxf(mx, __shfl_xor_sync(0xffffffffu, mx, o));
        float ex = expf(e - mx);
        float smv = ex;
        #pragma unroll
        for (int o = 16; o > 0; o >>= 1) smv += __shfl_xor_sync(0xffffffffu, smv, o);
        float w = ex / smv;

        ((float2*)(g_locs + (size_t)nq * 512))[s] = make_float2(lx, ly);
        g_wts[(size_t)nq * 256 + s] = w;
    }
}

// ---------------------------------------------------------------------------
// Kernel 3 (hot): bilinear gather + weighted aggregation of full input rows
// grid = NQ blocks, 8 warps (warp = head). Lane owns 8 channels.
// ---------------------------------------------------------------------------
__global__ __launch_bounds__(256) void ksamp(const float* __restrict__ input)
{
    int nq   = blockIdx.x;
    int n    = nq / LQ;
    int warp = threadIdx.x >> 5;
    int lane = threadIdx.x & 31;

    const float* base = input + (size_t)n * (LEN_IN * C_DIM);

    float2 L = ((const float2*)(g_locs + (size_t)nq * 512))[warp * 32 + lane];
    float  Wt = g_wts[(size_t)nq * 256 + warp * 32 + lane];
    float  Lx = L.x, Ly = L.y;

    float acc[8] = {0.f, 0.f, 0.f, 0.f, 0.f, 0.f, 0.f, 0.f};
    float bacc = 0.f;

#define CORNER(XI, YI, CWV)                                                     \
    do {                                                                        \
        int _x = (XI), _y = (YI);                                               \
        if (_x >= 0 && _x < Wl && _y >= 0 && _y < Wl) {                         \
            float _cw = (CWV);                                                  \
            const float4* _r = (const float4*)(baseL +                          \
                               (size_t)(_y * Wl + _x) * C_DIM);                 \
            float4 _v0 = _r[lane];                                              \
            float4 _v1 = _r[32 + lane];                                         \
            acc[0] = fmaf(_cw, _v0.x, acc[0]);                                  \
            acc[1] = fmaf(_cw, _v0.y, acc[1]);                                  \
            acc[2] = fmaf(_cw, _v0.z, acc[2]);                                  \
            acc[3] = fmaf(_cw, _v0.w, acc[3]);                                  \
            acc[4] = fmaf(_cw, _v1.x, acc[4]);                                  \
            acc[5] = fmaf(_cw, _v1.y, acc[5]);                                  \
            acc[6] = fmaf(_cw, _v1.z, acc[6]);                                  \
            acc[7] = fmaf(_cw, _v1.w, acc[7]);                                  \
            bacc += _cw;                                                        \
        }                                                                       \
    } while (0)

    #pragma unroll
    for (int l = 0; l < 4; ++l) {
        const int Wl     = 128 >> l;
        const int startl = (l == 0) ? 0 : (l == 1) ? 16384 : (l == 2) ? 20480 : 21504;
        const float fW   = (float)Wl;
        const float* baseL = base + (size_t)startl * C_DIM;
        #pragma unroll
        for (int p = 0; p < 8; ++p) {
            int s = l * 8 + p;
            float lx = __shfl_sync(0xffffffffu, Lx, s);
            float ly = __shfl_sync(0xffffffffu, Ly, s);
            float wt = __shfl_sync(0xffffffffu, Wt, s);

            float px = lx * fW - 0.5f;
            float py = ly * fW - 0.5f;
            float xf = floorf(px), yf = floorf(py);
            float fx = px - xf,    fy = py - yf;
            int   x0 = (int)xf,    y0 = (int)yf;
            float gx = 1.0f - fx,  gy = 1.0f - fy;

            CORNER(x0,     y0,     wt * gx * gy);
            CORNER(x0 + 1, y0,     wt * fx * gy);
            CORNER(x0,     y0 + 1, wt * gx * fy);
            CORNER(x0 + 1, y0 + 1, wt * fx * fy);
        }
    }
#undef CORNER

    float* ap = g_agg + ((size_t)nq * 8 + warp) * 256;
    ((float4*)ap)[lane]      = make_float4(acc[0], acc[1], acc[2], acc[3]);
    ((float4*)ap)[32 + lane] = make_float4(acc[4], acc[5], acc[6], acc[7]);
    if (lane == 0)
        g_beta[nq * 8 + warp] = bacc;
}

// ---------------------------------------------------------------------------
// Kernel 4 v2: per-head value projection, register-tiled
// grid = (75, 8): 32 queries x head h, 128 threads.
// Thread computes 2 queries x 4 d. dyn smem: as[32*260] + ws[256*32] (66 KB)
// ---------------------------------------------------------------------------
__global__ __launch_bounds__(128) void khead(const float* __restrict__ Wval,
                                             const float* __restrict__ bval)
{
    extern __shared__ float sh[];
    float* as = sh;                  // 32 * 260 (pad keeps multicast conflict-free + 16B aligned)
    float* ws = sh + 32 * 260;       // 256 * 32

    int h   = blockIdx.y;
    int q0  = blockIdx.x * 32;
    int tid = threadIdx.x;

    #pragma unroll
    for (int j = 0; j < 16; ++j) {
        int f4 = tid + j * 128;          // 0..2047
        int q  = f4 >> 6;                // 64 float4 per query row
        int c  = (f4 & 63) * 4;
        float4 v = *(const float4*)(g_agg + ((size_t)(q0 + q) * 8 + h) * 256 + c);
        *(float4*)(as + q * 260 + c) = v;
    }
    #pragma unroll
    for (int j = 0; j < 16; ++j) {
        int f4 = tid + j * 128;          // 0..2047
        int c  = f4 >> 3;
        int dd = (f4 & 7) * 4;
        *(float4*)(ws + c * 32 + dd) =
            *(const float4*)(Wval + (size_t)c * 256 + h * 32 + dd);
    }
    __syncthreads();

    int dg = (tid & 7) * 4;          // d-group within head: 0,4,...,28
    int qa = (tid >> 3) * 2;         // query pair: 0,2,...,30

    float a00 = 0.f, a01 = 0.f, a02 = 0.f, a03 = 0.f;
    float a10 = 0.f, a11 = 0.f, a12 = 0.f, a13 = 0.f;

    const float* asr0 = as + qa * 260;
    const float* asr1 = as + qa * 260 + 260;

    #pragma unroll 4
    for (int c = 0; c < 256; ++c) {
        float4 w = *(const float4*)(ws + c * 32 + dg);
        float x0 = asr0[c];
        float x1 = asr1[c];
        a00 = fmaf(x0, w.x, a00);
        a01 = fmaf(x0, w.y, a01);
        a02 = fmaf(x0, w.z, a02);
        a03 = fmaf(x0, w.w, a03);
        a10 = fmaf(x1, w.x, a10);
        a11 = fmaf(x1, w.y, a11);
        a12 = fmaf(x1, w.z, a12);
        a13 = fmaf(x1, w.w, a13);
    }

    int d = h * 32 + dg;
    float4 bv = *(const float4*)(bval + d);
    float be0 = g_beta[(q0 + qa) * 8 + h];
    float be1 = g_beta[(q0 + qa + 1) * 8 + h];
    *(float4*)(g_outcore + (size_t)(q0 + qa) * 256 + d) =
        make_float4(a00 + be0 * bv.x, a01 + be0 * bv.y,
                    a02 + be0 * bv.z, a03 + be0 * bv.w);
    *(float4*)(g_outcore + (size_t)(q0 + qa + 1) * 256 + d) =
        make_float4(a10 + be1 * bv.x, a11 + be1 * bv.y,
                    a12 + be1 * bv.z, a13 + be1 * bv.w);
}

// ---------------------------------------------------------------------------
// Kernel 5 v2: output projection with cp.async double-buffered weight tiles
// grid = 300 blocks (8 queries), 256 threads.
// dyn smem: xs[8*256] + 2 x wtile[32*256]  (72 KB)
// ---------------------------------------------------------------------------
__device__ __forceinline__ void stage_out(const float* __restrict__ W,
                                          int k0, float* buf, int tid)
{
    #pragma unroll
    for (int j = 0; j < 8; ++j) {
        int f4 = tid + j * 256;          // 0..2047
        int r  = f4 >> 6;
        int c4 = (f4 & 63) * 4;
        cp16(s2u(buf + r * 256 + c4), W + (size_t)(k0 + r) * 256 + c4);
    }
    CP_COMMIT();
}

__global__ __launch_bounds__(256) void kout(const float* __restrict__ Wout,
                                            const float* __restrict__ bout,
                                            float* __restrict__ out)
{
    extern __shared__ float sk[];
    float* xs  = sk;                 // 2048 floats
    float* wb0 = sk + 2048;          // 8192
    float* wb1 = sk + 2048 + 8192;   // 8192

    int q0  = blockIdx.x * 8;
    int tid = threadIdx.x;

    stage_out(Wout, 0,  wb0, tid);
    stage_out(Wout, 32, wb1, tid);

    for (int i = tid; i < 2048; i += 256)
        xs[i] = g_outcore[(size_t)q0 * 256 + i];

    float acc[8];
    #pragma unroll
    for (int i = 0; i < 8; ++i) acc[i] = 0.f;

    for (int t = 0; t < 8; ++t) {
        if (t < 7) { CP_WAIT_1(); } else { CP_WAIT_0(); }
        __syncthreads();
        const float* buf = (t & 1) ? wb1 : wb0;
        #pragma unroll 4
        for (int r = 0; r < 32; ++r) {
            float w = buf[r * 256 + tid];
            int k = t * 32 + r;
            #pragma unroll
            for (int i = 0; i < 8; ++i)
                acc[i] = fmaf(xs[i * 256 + k], w, acc[i]);
        }
        __syncthreads();
        if (t + 2 < 8)
            stage_out(Wout, (t + 2) * 32, (t & 1) ? wb1 : wb0, tid);
    }

    float b = bout[tid];
    #pragma unroll
    for (int i = 0; i < 8; ++i)
        out[(size_t)(q0 + i) * 256 + tid] = acc[i] + b;
}

// ---------------------------------------------------------------------------
// Launch
// ---------------------------------------------------------------------------
extern "C" void kernel_launch(void* const* d_in, const int* in_sizes, int n_in,
                              void* d_out, int out_size)
{
    const float* query = (const float*)d_in[0];
    const float* masks = (const float*)d_in[2];
    const float* input = (const float*)d_in[4];
    const float* Woff  = (const float*)d_in[8];
    const float* boff  = (const float*)d_in[9];
    const float* Wattn = (const float*)d_in[10];
    const float* battn = (const float*)d_in[11];
    const float* Wval  = (const float*)d_in[12];
    const float* bval  = (const float*)d_in[13];
    const float* Wout  = (const float*)d_in[14];
    const float* bout  = (const float*)d_in[15];
    float* out = (float*)d_out;

    static const int SMEM_PP   = (4096 + 2 * 12288) * 4;   // 114688
    static const int SMEM_HEAD = (32 * 260 + 256 * 32) * 4; // 66048
    static const int SMEM_OUT  = (2048 + 2 * 8192) * 4;     // 73728

    cudaFuncSetAttribute(kprojpts, cudaFuncAttributeMaxDynamicSharedMemorySize, SMEM_PP);
    cudaFuncSetAttribute(khead,    cudaFuncAttributeMaxDynamicSharedMemorySize, SMEM_HEAD);
    cudaFuncSetAttribute(kout,     cudaFuncAttributeMaxDynamicSharedMemorySize, SMEM_OUT);

    kbox    <<<NQ, 256>>>(masks);
    kprojpts<<<150, 256, SMEM_PP>>>(query, Woff, boff, Wattn, battn);
    ksamp   <<<NQ, 256>>>(input);
    khead   <<<dim3(75, 8), 128, SMEM_HEAD>>>(Wval, bval);
    kout    <<<300, 256, SMEM_OUT>>>(Wout, bout, out);
}